// round 2
// baseline (speedup 1.0000x reference)
#include <cuda_runtime.h>
#include <math.h>

#define BB 2
#define TT 20
#define VV 256
#define PPB (TT*VV)          // 5120 points per batch
#define NPTS (BB*PPB)        // 10240
#define NSPLIT 8
#define QCHUNK (PPB/NSPLIT)  // 640
#define QTILE 64
#define BLKP 64              // threads per k4 CTA (one p-row each)

// ---- device scratch (no allocations allowed) ----
__device__ float4 g_Wsmall[2048];        // folded W_fuse_local @ W_comp, per-c float4
__device__ float  g_bcomp4[4];           // W_fuse_local @ b_comp
__device__ float4 g_comp2[1024];         // 4-channel 32x32 feature map (pixel-major)
// Q/K/V stored DIM-INTERLEAVED per point: float4 #0 = (d0,d4,d1,d5), #1 = (d2,d6,d3,d7)
__device__ float4 g_Q4[NPTS*2];
__device__ float4 g_K4[NPTS*2];
__device__ float4 g_V4[NPTS*2];
__device__ float4 g_part4[NSPLIT*NPTS*2];

// ---- packed f32x2 helpers (FFMA2 only reachable via PTX on sm_103a) ----
__device__ __forceinline__ unsigned long long pk2(float lo, float hi) {
    unsigned long long r;
    asm("mov.b64 %0, {%1, %2};" : "=l"(r) : "f"(lo), "f"(hi));
    return r;
}
__device__ __forceinline__ void upk2(unsigned long long v, float& lo, float& hi) {
    asm("mov.b64 {%0, %1}, %2;" : "=f"(lo), "=f"(hi) : "l"(v));
}
__device__ __forceinline__ unsigned long long mul2(unsigned long long a, unsigned long long b) {
    unsigned long long r;
    asm("mul.rn.f32x2 %0, %1, %2;" : "=l"(r) : "l"(a), "l"(b));
    return r;
}
__device__ __forceinline__ unsigned long long fma2(unsigned long long a, unsigned long long b,
                                                   unsigned long long c) {
    unsigned long long r;
    asm("fma.rn.f32x2 %0, %1, %2, %3;" : "=l"(r) : "l"(a), "l"(b), "l"(c));
    return r;
}

// ---------------------------------------------------------------------------
// k1: Wsmall[j][c] = sum_cc W_fuse[j][4+cc] * W_comp[cc][c]; bias fold; zero comp2
// grid: 8 x 256 (one c per thread)
// ---------------------------------------------------------------------------
__global__ void k1_prep(const float* __restrict__ W_fuse,
                        const float* __restrict__ W_comp,
                        const float* __restrict__ b_comp) {
    int tid = threadIdx.x;
    int c = blockIdx.x * 256 + tid;

    if (blockIdx.x == 0) {
        if (tid < 4) {
            float s = 0.f;
            for (int cc = 0; cc < 256; cc++)
                s += W_fuse[tid * 260 + 4 + cc] * b_comp[cc];
            g_bcomp4[tid] = s;
        }
        for (int i = tid; i < 1024; i += 256)
            g_comp2[i] = make_float4(0.f, 0.f, 0.f, 0.f);
    }

    float a0 = 0.f, a1 = 0.f, a2 = 0.f, a3 = 0.f;
#pragma unroll 8
    for (int cc = 0; cc < 256; cc++) {
        float w = W_comp[cc * 2048 + c];
        a0 = fmaf(W_fuse[0 * 260 + 4 + cc], w, a0);
        a1 = fmaf(W_fuse[1 * 260 + 4 + cc], w, a1);
        a2 = fmaf(W_fuse[2 * 260 + 4 + cc], w, a2);
        a3 = fmaf(W_fuse[3 * 260 + 4 + cc], w, a3);
    }
    g_Wsmall[c] = make_float4(a0, a1, a2, a3);
}

// ---------------------------------------------------------------------------
// k2: comp2[px] += sum_{c in chunk} Wsmall[c] * metadata[c][px]  (+ bias once)
// grid: (8 px-tiles, 16 c-chunks) x 128
// ---------------------------------------------------------------------------
__global__ void k2_comp2(const float* __restrict__ meta) {
    int px = blockIdx.x * 128 + threadIdx.x;    // 0..1023
    int c0 = blockIdx.y * 128;
    float a0 = 0.f, a1 = 0.f, a2 = 0.f, a3 = 0.f;
#pragma unroll 8
    for (int ci = 0; ci < 128; ci++) {
        int c = c0 + ci;
        float m = meta[c * 1024 + px];
        float4 w = g_Wsmall[c];
        a0 = fmaf(w.x, m, a0);
        a1 = fmaf(w.y, m, a1);
        a2 = fmaf(w.z, m, a2);
        a3 = fmaf(w.w, m, a3);
    }
    if (blockIdx.y == 0) {
        a0 += g_bcomp4[0]; a1 += g_bcomp4[1]; a2 += g_bcomp4[2]; a3 += g_bcomp4[3];
    }
    float* dst = (float*)&g_comp2[px];
    atomicAdd(dst + 0, a0);
    atomicAdd(dst + 1, a1);
    atomicAdd(dst + 2, a2);
    atomicAdd(dst + 3, a3);
}

// ---------------------------------------------------------------------------
// k3: per-point PE + LSTM step + bilinear sample + fuse + Q/K/V (interleaved store)
// grid: 40 x 256 (one point per thread)
// ---------------------------------------------------------------------------
__global__ void k3_qkv(const float* __restrict__ x, const float* __restrict__ ac,
                       const float* __restrict__ W_ih, const float* __restrict__ b_ih,
                       const float* __restrict__ b_hh,
                       const float* __restrict__ W_fuse, const float* __restrict__ b_fuse,
                       const float* __restrict__ W_fc,  const float* __restrict__ b_fc,
                       const float* __restrict__ W_fc2, const float* __restrict__ b_fc2,
                       const float* __restrict__ W_fc3, const float* __restrict__ b_fc3) {
    int p = blockIdx.x * 256 + threadIdx.x;
    if (p >= NPTS) return;
    int b = p / PPB, r = p % PPB, t = r / VV, v = r % VV;

    // positional encoding: c=2 -> pe = (sin t, cos t)
    float x0 = x[((b * TT + t) * VV + v) * 2 + 0] + sinf((float)t);
    float x1 = x[((b * TT + t) * VV + v) * 2 + 1] + cosf((float)t);

    // single-step LSTM (h0=c0=0), gate order i,f,g,o (f unused since c0=0)
    float h[4];
#pragma unroll
    for (int j = 0; j < 4; j++) {
        float gi = fmaf(x0, W_ih[(0 + j) * 2 + 0], fmaf(x1, W_ih[(0 + j) * 2 + 1],
                        b_ih[0 + j] + b_hh[0 + j]));
        float gg = fmaf(x0, W_ih[(8 + j) * 2 + 0], fmaf(x1, W_ih[(8 + j) * 2 + 1],
                        b_ih[8 + j] + b_hh[8 + j]));
        float go = fmaf(x0, W_ih[(12 + j) * 2 + 0], fmaf(x1, W_ih[(12 + j) * 2 + 1],
                        b_ih[12 + j] + b_hh[12 + j]));
        float si = 1.f / (1.f + expf(-gi));
        float so = 1.f / (1.f + expf(-go));
        float cst = si * tanhf(gg);
        h[j] = so * tanhf(cst);
    }

    // bilinear grid sample on folded 4-ch map (align_corners=False, zero pad)
    float cx = ac[((b * 2 + 0) * TT + t) * VV + v];
    float cy = ac[((b * 2 + 1) * TT + t) * VV + v];
    float fx = cx * (1.f / 16.f) - 0.5f;
    float fy = cy * (1.f / 16.f) - 0.5f;
    float x0f = floorf(fx), y0f = floorf(fy);
    int ix0 = (int)x0f, iy0 = (int)y0f;
    float wx1 = fx - x0f, wx0 = 1.f - wx1;
    float wy1 = fy - y0f, wy0 = 1.f - wy1;
    float l0 = 0.f, l1 = 0.f, l2 = 0.f, l3 = 0.f;
#pragma unroll
    for (int dy = 0; dy < 2; dy++) {
#pragma unroll
        for (int dx = 0; dx < 2; dx++) {
            int xx = ix0 + dx, yy = iy0 + dy;
            if (xx >= 0 && xx < 32 && yy >= 0 && yy < 32) {
                float w = (dx ? wx1 : wx0) * (dy ? wy1 : wy0);
                float4 cv = g_comp2[yy * 32 + xx];
                l0 = fmaf(w, cv.x, l0);
                l1 = fmaf(w, cv.y, l1);
                l2 = fmaf(w, cv.z, l2);
                l3 = fmaf(w, cv.w, l3);
            }
        }
    }

    // fuse: Xf = W_fuse[:, :4] @ h + local + b_fuse
    float Xf[4] = {l0, l1, l2, l3};
#pragma unroll
    for (int j = 0; j < 4; j++) {
        float s = Xf[j] + b_fuse[j];
#pragma unroll
        for (int k = 0; k < 4; k++) s = fmaf(W_fuse[j * 260 + k], h[k], s);
        Xf[j] = s;
    }

    float Q[8], K[8], Vq[8];
#pragma unroll
    for (int d = 0; d < 8; d++) {
        float s = b_fc[d];
#pragma unroll
        for (int k = 0; k < 4; k++) s = fmaf(W_fc[d * 4 + k], Xf[k], s);
        Q[d] = s;
        K[d]  = fmaf(x0, W_fc2[d * 2 + 0], fmaf(x1, W_fc2[d * 2 + 1], b_fc2[d]));
        Vq[d] = fmaf(x0, W_fc3[d * 2 + 0], fmaf(x1, W_fc3[d * 2 + 1], b_fc3[d]));
    }
    // interleaved pair layout: (d0,d4,d1,d5) / (d2,d6,d3,d7) for packed f32x2 math
    g_Q4[p * 2 + 0] = make_float4(Q[0], Q[4], Q[1], Q[5]);
    g_Q4[p * 2 + 1] = make_float4(Q[2], Q[6], Q[3], Q[7]);
    g_K4[p * 2 + 0] = make_float4(K[0], K[4], K[1], K[5]);
    g_K4[p * 2 + 1] = make_float4(K[2], K[6], K[3], K[7]);
    g_V4[p * 2 + 0] = make_float4(Vq[0], Vq[4], Vq[1], Vq[5]);
    g_V4[p * 2 + 1] = make_float4(Vq[2], Vq[6], Vq[3], Vq[7]);
}

// ---------------------------------------------------------------------------
// k4: attention partials with packed f32x2 math.
// out[p] += sum_{q in chunk} sigmoid(Q[p].K[q]) * V[q]
// grid: (80 p-tiles, NSPLIT q-chunks, B) x 64 threads; one p-row per thread
// ---------------------------------------------------------------------------
__global__ void __launch_bounds__(BLKP) k4_attn() {
    int tid = threadIdx.x;
    int b = blockIdx.z;
    int p = blockIdx.x * BLKP + tid;         // local p in [0, PPB)
    int split = blockIdx.y;
    int pg = b * PPB + p;

    float4 qaf = g_Q4[pg * 2 + 0];
    float4 qbf = g_Q4[pg * 2 + 1];
    ulonglong2 qA = *reinterpret_cast<ulonglong2*>(&qaf);   // (Q0,Q4) (Q1,Q5)
    ulonglong2 qB = *reinterpret_cast<ulonglong2*>(&qbf);   // (Q2,Q6) (Q3,Q7)

    unsigned long long acc0 = 0ull, acc1 = 0ull, acc2 = 0ull, acc3 = 0ull; // pairs (o_d,o_{d+4})

    __shared__ float4 sK[QTILE * 2];
    __shared__ float4 sV[QTILE * 2];

    int qbase = b * PPB + split * QCHUNK;
    for (int tile = 0; tile < QCHUNK / QTILE; tile++) {
        int qi = qbase + tile * QTILE + tid;
        __syncthreads();
        sK[tid * 2 + 0] = g_K4[qi * 2 + 0];
        sK[tid * 2 + 1] = g_K4[qi * 2 + 1];
        sV[tid * 2 + 0] = g_V4[qi * 2 + 0];
        sV[tid * 2 + 1] = g_V4[qi * 2 + 1];
        __syncthreads();
#pragma unroll 8
        for (int j = 0; j < QTILE; j++) {
            float4 k0f = sK[j * 2 + 0];
            float4 k1f = sK[j * 2 + 1];
            ulonglong2 kA = *reinterpret_cast<ulonglong2*>(&k0f);
            ulonglong2 kB = *reinterpret_cast<ulonglong2*>(&k1f);
            unsigned long long d = mul2(qA.x, kA.x);
            d = fma2(qA.y, kA.y, d);
            d = fma2(qB.x, kB.x, d);
            d = fma2(qB.y, kB.y, d);
            float dlo, dhi;
            upk2(d, dlo, dhi);
            float s = dlo + dhi;
            float pr = __fdividef(1.f, 1.f + __expf(-s));
            unsigned long long prp = pk2(pr, pr);
            float4 v0f = sV[j * 2 + 0];
            float4 v1f = sV[j * 2 + 1];
            ulonglong2 vA = *reinterpret_cast<ulonglong2*>(&v0f);
            ulonglong2 vB = *reinterpret_cast<ulonglong2*>(&v1f);
            acc0 = fma2(prp, vA.x, acc0);
            acc1 = fma2(prp, vA.y, acc1);
            acc2 = fma2(prp, vB.x, acc2);
            acc3 = fma2(prp, vB.y, acc3);
        }
    }
    // store packed pairs directly (k5 un-interleaves)
    float a0l, a0h, a1l, a1h, a2l, a2h, a3l, a3h;
    upk2(acc0, a0l, a0h); upk2(acc1, a1l, a1h);
    upk2(acc2, a2l, a2h); upk2(acc3, a3l, a3h);
    int oi = ((split * BB + b) * PPB + p) * 2;
    g_part4[oi + 0] = make_float4(a0l, a0h, a1l, a1h);   // (o0,o4,o1,o5)
    g_part4[oi + 1] = make_float4(a2l, a2h, a3l, a3h);   // (o2,o6,o3,o7)
}

// ---------------------------------------------------------------------------
// k5: reduce partials, threshold, project 8->5, write transposed (b, 5, t, n)
// grid: 40 x 256
// ---------------------------------------------------------------------------
__global__ void k5_final(const float* __restrict__ W_out, const float* __restrict__ b_out,
                         float* __restrict__ out) {
    int p = blockIdx.x * 256 + threadIdx.x;
    if (p >= NPTS) return;
    int b = p / PPB, r = p % PPB, t = r / VV, v = r % VV;

    float o[8] = {0, 0, 0, 0, 0, 0, 0, 0};
#pragma unroll
    for (int s = 0; s < NSPLIT; s++) {
        int oi = ((s * BB + b) * PPB + r) * 2;
        float4 a0 = g_part4[oi + 0];   // (o0,o4,o1,o5)
        float4 a1 = g_part4[oi + 1];   // (o2,o6,o3,o7)
        o[0] += a0.x; o[4] += a0.y; o[1] += a0.z; o[5] += a0.w;
        o[2] += a1.x; o[6] += a1.y; o[3] += a1.z; o[7] += a1.w;
    }
#pragma unroll
    for (int d = 0; d < 8; d++) o[d] = (o[d] > 0.5f) ? o[d] : 0.f;
#pragma unroll
    for (int dd = 0; dd < 5; dd++) {
        float y = b_out[dd];
#pragma unroll
        for (int d = 0; d < 8; d++) y = fmaf(W_out[dd * 8 + d], o[d], y);
        out[((b * 5 + dd) * TT + t) * VV + v] = y;
    }
}

// ---------------------------------------------------------------------------
extern "C" void kernel_launch(void* const* d_in, const int* in_sizes, int n_in,
                              void* d_out, int out_size) {
    const float* x      = (const float*)d_in[0];
    const float* ac     = (const float*)d_in[1];
    const float* meta   = (const float*)d_in[2];
    const float* W_ih   = (const float*)d_in[3];
    // d_in[4] = W_hh (unused: h0 = 0)
    const float* b_ih   = (const float*)d_in[5];
    const float* b_hh   = (const float*)d_in[6];
    const float* W_comp = (const float*)d_in[7];
    const float* b_comp = (const float*)d_in[8];
    const float* W_fuse = (const float*)d_in[9];
    const float* b_fuse = (const float*)d_in[10];
    const float* W_fc   = (const float*)d_in[11];
    const float* b_fc   = (const float*)d_in[12];
    const float* W_fc2  = (const float*)d_in[13];
    const float* b_fc2  = (const float*)d_in[14];
    const float* W_fc3  = (const float*)d_in[15];
    const float* b_fc3  = (const float*)d_in[16];
    const float* W_out  = (const float*)d_in[17];
    const float* b_out  = (const float*)d_in[18];
    float* out = (float*)d_out;

    k1_prep<<<8, 256>>>(W_fuse, W_comp, b_comp);
    k2_comp2<<<dim3(8, 16), 128>>>(meta);
    k3_qkv<<<40, 256>>>(x, ac, W_ih, b_ih, b_hh, W_fuse, b_fuse,
                        W_fc, b_fc, W_fc2, b_fc2, W_fc3, b_fc3);
    k4_attn<<<dim3(PPB / BLKP, NSPLIT, BB), BLKP>>>();
    k5_final<<<40, 256>>>(W_out, b_out, out);
}

// round 5
// speedup vs baseline: 1.1856x; 1.1856x over previous
#include <cuda_runtime.h>
#include <math.h>

#define BB 2
#define TT 20
#define VV 256
#define PPB (TT*VV)          // 5120 points per batch
#define NPTS (BB*PPB)        // 10240
#define NSPLIT 32
#define QCHUNK (PPB/NSPLIT)  // 160
#define BLKP 128             // threads per k4 CTA
#define PPER 2               // p rows per thread
#define PTILE (BLKP*PPER)    // 256

// ---- device scratch (no allocations allowed) ----
__device__ float4 g_Wsmall[2048];        // folded W_fuse_local @ W_comp (per-c float4)
__device__ float  g_bcomp4[4];           // W_fuse_local @ b_comp
__device__ float4 g_comp2[1024];         // 4-channel 32x32 feature map (pixel-major)
// Q/K/V dim-interleaved per point: float4 #0=(d0,d4,d1,d5), #1=(d2,d6,d3,d7)
// Q additionally pre-scaled by -log2(e) so k4 sigmoid = rcp(1+ex2(Q'.K))
__device__ float4 g_Q4[NPTS*2];
__device__ float4 g_K4[NPTS*2];
__device__ float4 g_V4[NPTS*2];
__device__ float4 g_part4[NSPLIT*NPTS*2];

// ---- packed f32x2 + MUFU helpers ----
__device__ __forceinline__ unsigned long long pk2(float lo, float hi) {
    unsigned long long r;
    asm("mov.b64 %0, {%1, %2};" : "=l"(r) : "f"(lo), "f"(hi));
    return r;
}
__device__ __forceinline__ void upk2(unsigned long long v, float& lo, float& hi) {
    asm("mov.b64 {%0, %1}, %2;" : "=f"(lo), "=f"(hi) : "l"(v));
}
__device__ __forceinline__ unsigned long long mul2(unsigned long long a, unsigned long long b) {
    unsigned long long r;
    asm("mul.rn.f32x2 %0, %1, %2;" : "=l"(r) : "l"(a), "l"(b));
    return r;
}
__device__ __forceinline__ unsigned long long fma2(unsigned long long a, unsigned long long b,
                                                   unsigned long long c) {
    unsigned long long r;
    asm("fma.rn.f32x2 %0, %1, %2, %3;" : "=l"(r) : "l"(a), "l"(b), "l"(c));
    return r;
}
__device__ __forceinline__ float ex2f(float x) {
    float r; asm("ex2.approx.f32 %0, %1;" : "=f"(r) : "f"(x)); return r;
}
__device__ __forceinline__ float rcpf(float x) {
    float r; asm("rcp.approx.f32 %0, %1;" : "=f"(r) : "f"(x)); return r;
}
#define NLOG2E (-1.4426950408889634f)
__device__ __forceinline__ float fast_sigmoid(float s) {      // 1/(1+e^-s), err ~1e-6
    return rcpf(1.f + ex2f(NLOG2E * s));
}
__device__ __forceinline__ float fast_tanh(float x) {          // (t-1)/(t+1), t=e^{2x}
    float t = ex2f(2.8853900817779268f * x);                   // 2*log2(e)
    float r = rcpf(t + 1.f);
    return (t - 1.f) * r;
}

// ---------------------------------------------------------------------------
// k1: Wsmall[c][j] = sum_cc W_fuse[j][4+cc] * W_comp[cc][c]; bias fold; zero comp2
// grid: 8 x 256 (one c per thread); W_fuse staged in smem
// ---------------------------------------------------------------------------
__global__ void k1_prep(const float* __restrict__ W_fuse,
                        const float* __restrict__ W_comp,
                        const float* __restrict__ b_comp) {
    __shared__ float sWf[4 * 256];
    int tid = threadIdx.x;
    int c = blockIdx.x * 256 + tid;

#pragma unroll
    for (int i = tid; i < 1024; i += 256)
        sWf[i] = W_fuse[(i >> 8) * 260 + 4 + (i & 255)];
    __syncthreads();

    if (blockIdx.x == 0) {
        if (tid < 128) {                       // one warp per output j, shfl reduce
            int j = tid >> 5, lane = tid & 31;
            float s = 0.f;
#pragma unroll
            for (int cc = lane; cc < 256; cc += 32)
                s += sWf[j * 256 + cc] * b_comp[cc];
#pragma unroll
            for (int o = 16; o > 0; o >>= 1)
                s += __shfl_down_sync(0xffffffffu, s, o);
            if (lane == 0) g_bcomp4[j] = s;
        }
        for (int i = tid; i < 1024; i += 256)
            g_comp2[i] = make_float4(0.f, 0.f, 0.f, 0.f);
    }

    float a0 = 0.f, a1 = 0.f, a2 = 0.f, a3 = 0.f;
#pragma unroll 16
    for (int cc = 0; cc < 256; cc++) {
        float w = W_comp[cc * 2048 + c];
        a0 = fmaf(sWf[0 * 256 + cc], w, a0);
        a1 = fmaf(sWf[1 * 256 + cc], w, a1);
        a2 = fmaf(sWf[2 * 256 + cc], w, a2);
        a3 = fmaf(sWf[3 * 256 + cc], w, a3);
    }
    g_Wsmall[c] = make_float4(a0, a1, a2, a3);
}

// ---------------------------------------------------------------------------
// k2: comp2[px] += sum_{c in 64-chunk} Wsmall[c] * metadata[c][px] (+ bias once)
// grid: (8 px-tiles, 32 c-chunks) x 128
// ---------------------------------------------------------------------------
__global__ void k2_comp2(const float* __restrict__ meta) {
    int px = blockIdx.x * 128 + threadIdx.x;    // 0..1023
    int c0 = blockIdx.y * 64;
    float a0 = 0.f, a1 = 0.f, a2 = 0.f, a3 = 0.f;
#pragma unroll 16
    for (int ci = 0; ci < 64; ci++) {
        int c = c0 + ci;
        float m = meta[c * 1024 + px];
        float4 w = g_Wsmall[c];
        a0 = fmaf(w.x, m, a0);
        a1 = fmaf(w.y, m, a1);
        a2 = fmaf(w.z, m, a2);
        a3 = fmaf(w.w, m, a3);
    }
    if (blockIdx.y == 0) {
        a0 += g_bcomp4[0]; a1 += g_bcomp4[1]; a2 += g_bcomp4[2]; a3 += g_bcomp4[3];
    }
    float* dst = (float*)&g_comp2[px];
    atomicAdd(dst + 0, a0);
    atomicAdd(dst + 1, a1);
    atomicAdd(dst + 2, a2);
    atomicAdd(dst + 3, a3);
}

// ---------------------------------------------------------------------------
// k3: per-point PE + LSTM step + bilinear sample + fuse + Q/K/V
// grid: 40 x 256 (one point per thread)
// ---------------------------------------------------------------------------
__global__ void k3_qkv(const float* __restrict__ x, const float* __restrict__ ac,
                       const float* __restrict__ W_ih, const float* __restrict__ b_ih,
                       const float* __restrict__ b_hh,
                       const float* __restrict__ W_fuse, const float* __restrict__ b_fuse,
                       const float* __restrict__ W_fc,  const float* __restrict__ b_fc,
                       const float* __restrict__ W_fc2, const float* __restrict__ b_fc2,
                       const float* __restrict__ W_fc3, const float* __restrict__ b_fc3) {
    int p = blockIdx.x * 256 + threadIdx.x;
    if (p >= NPTS) return;
    int b = p / PPB, r = p % PPB, t = r / VV, v = r % VV;

    // positional encoding: c=2 -> pe = (sin t, cos t); |t|<20 so __sinf is safe
    float x0 = x[((b * TT + t) * VV + v) * 2 + 0] + __sinf((float)t);
    float x1 = x[((b * TT + t) * VV + v) * 2 + 1] + __cosf((float)t);

    // single-step LSTM (h0=c0=0), gate order i,f,g,o (f unused since c0=0)
    float h[4];
#pragma unroll
    for (int j = 0; j < 4; j++) {
        float gi = fmaf(x0, W_ih[(0 + j) * 2 + 0], fmaf(x1, W_ih[(0 + j) * 2 + 1],
                        b_ih[0 + j] + b_hh[0 + j]));
        float gg = fmaf(x0, W_ih[(8 + j) * 2 + 0], fmaf(x1, W_ih[(8 + j) * 2 + 1],
                        b_ih[8 + j] + b_hh[8 + j]));
        float go = fmaf(x0, W_ih[(12 + j) * 2 + 0], fmaf(x1, W_ih[(12 + j) * 2 + 1],
                        b_ih[12 + j] + b_hh[12 + j]));
        float cst = fast_sigmoid(gi) * fast_tanh(gg);
        h[j] = fast_sigmoid(go) * fast_tanh(cst);
    }

    // bilinear grid sample on folded 4-ch map (align_corners=False, zero pad)
    float cx = ac[((b * 2 + 0) * TT + t) * VV + v];
    float cy = ac[((b * 2 + 1) * TT + t) * VV + v];
    float fx = cx * (1.f / 16.f) - 0.5f;
    float fy = cy * (1.f / 16.f) - 0.5f;
    float x0f = floorf(fx), y0f = floorf(fy);
    int ix0 = (int)x0f, iy0 = (int)y0f;
    float wx1 = fx - x0f, wx0 = 1.f - wx1;
    float wy1 = fy - y0f, wy0 = 1.f - wy1;
    float l0 = 0.f, l1 = 0.f, l2 = 0.f, l3 = 0.f;
#pragma unroll
    for (int dy = 0; dy < 2; dy++) {
#pragma unroll
        for (int dx = 0; dx < 2; dx++) {
            int xx = ix0 + dx, yy = iy0 + dy;
            if (xx >= 0 && xx < 32 && yy >= 0 && yy < 32) {
                float w = (dx ? wx1 : wx0) * (dy ? wy1 : wy0);
                float4 cv = g_comp2[yy * 32 + xx];
                l0 = fmaf(w, cv.x, l0);
                l1 = fmaf(w, cv.y, l1);
                l2 = fmaf(w, cv.z, l2);
                l3 = fmaf(w, cv.w, l3);
            }
        }
    }

    // fuse: Xf = W_fuse[:, :4] @ h + local + b_fuse
    float Xf[4] = {l0, l1, l2, l3};
#pragma unroll
    for (int j = 0; j < 4; j++) {
        float s = Xf[j] + b_fuse[j];
#pragma unroll
        for (int k = 0; k < 4; k++) s = fmaf(W_fuse[j * 260 + k], h[k], s);
        Xf[j] = s;
    }

    float Q[8], K[8], Vq[8];
#pragma unroll
    for (int d = 0; d < 8; d++) {
        float s = b_fc[d];
#pragma unroll
        for (int k = 0; k < 4; k++) s = fmaf(W_fc[d * 4 + k], Xf[k], s);
        Q[d] = NLOG2E * s;   // fold -log2(e) for k4's ex2-based sigmoid
        K[d]  = fmaf(x0, W_fc2[d * 2 + 0], fmaf(x1, W_fc2[d * 2 + 1], b_fc2[d]));
        Vq[d] = fmaf(x0, W_fc3[d * 2 + 0], fmaf(x1, W_fc3[d * 2 + 1], b_fc3[d]));
    }
    // interleaved pair layout: (d0,d4,d1,d5) / (d2,d6,d3,d7) for packed f32x2 math
    g_Q4[p * 2 + 0] = make_float4(Q[0], Q[4], Q[1], Q[5]);
    g_Q4[p * 2 + 1] = make_float4(Q[2], Q[6], Q[3], Q[7]);
    g_K4[p * 2 + 0] = make_float4(K[0], K[4], K[1], K[5]);
    g_K4[p * 2 + 1] = make_float4(K[2], K[6], K[3], K[7]);
    g_V4[p * 2 + 0] = make_float4(Vq[0], Vq[4], Vq[1], Vq[5]);
    g_V4[p * 2 + 1] = make_float4(Vq[2], Vq[6], Vq[3], Vq[7]);
}

// ---------------------------------------------------------------------------
// k4: attention partials, packed f32x2, 2 p-rows per thread.
// grid: (20 p-tiles, 32 q-chunks, B) x 128
// ---------------------------------------------------------------------------
__global__ void __launch_bounds__(BLKP) k4_attn() {
    int tid = threadIdx.x;
    int b = blockIdx.z;
    int split = blockIdx.y;
    int p0 = blockIdx.x * PTILE + tid;       // and p1 = p0 + BLKP
    int pg0 = b * PPB + p0;
    int pg1 = pg0 + BLKP;

    __shared__ float4 sK[QCHUNK * 2];
    __shared__ float4 sV[QCHUNK * 2];

    int qbase2 = (b * PPB + split * QCHUNK) * 2;
#pragma unroll
    for (int i = tid; i < QCHUNK * 2; i += BLKP) sK[i] = g_K4[qbase2 + i];
#pragma unroll
    for (int i = tid; i < QCHUNK * 2; i += BLKP) sV[i] = g_V4[qbase2 + i];

    float4 q0af = g_Q4[pg0 * 2 + 0], q0bf = g_Q4[pg0 * 2 + 1];
    float4 q1af = g_Q4[pg1 * 2 + 0], q1bf = g_Q4[pg1 * 2 + 1];
    ulonglong2 q0A = *reinterpret_cast<ulonglong2*>(&q0af);
    ulonglong2 q0B = *reinterpret_cast<ulonglong2*>(&q0bf);
    ulonglong2 q1A = *reinterpret_cast<ulonglong2*>(&q1af);
    ulonglong2 q1B = *reinterpret_cast<ulonglong2*>(&q1bf);

    unsigned long long a00 = 0, a01 = 0, a02 = 0, a03 = 0;
    unsigned long long a10 = 0, a11 = 0, a12 = 0, a13 = 0;

    __syncthreads();

#pragma unroll 4
    for (int j = 0; j < QCHUNK; j++) {
        float4 k0f = sK[j * 2 + 0];
        float4 k1f = sK[j * 2 + 1];
        ulonglong2 kA = *reinterpret_cast<ulonglong2*>(&k0f);
        ulonglong2 kB = *reinterpret_cast<ulonglong2*>(&k1f);

        unsigned long long d0 = mul2(q0A.x, kA.x);
        d0 = fma2(q0A.y, kA.y, d0);
        d0 = fma2(q0B.x, kB.x, d0);
        d0 = fma2(q0B.y, kB.y, d0);
        unsigned long long d1 = mul2(q1A.x, kA.x);
        d1 = fma2(q1A.y, kA.y, d1);
        d1 = fma2(q1B.x, kB.x, d1);
        d1 = fma2(q1B.y, kB.y, d1);

        float u0l, u0h, u1l, u1h;
        upk2(d0, u0l, u0h);
        upk2(d1, u1l, u1h);
        // Q pre-scaled by -log2e: sigmoid = rcp(1 + ex2(u))
        float pr0 = rcpf(1.f + ex2f(u0l + u0h));
        float pr1 = rcpf(1.f + ex2f(u1l + u1h));
        unsigned long long pp0 = pk2(pr0, pr0);
        unsigned long long pp1 = pk2(pr1, pr1);

        float4 v0f = sV[j * 2 + 0];
        float4 v1f = sV[j * 2 + 1];
        ulonglong2 vA = *reinterpret_cast<ulonglong2*>(&v0f);
        ulonglong2 vB = *reinterpret_cast<ulonglong2*>(&v1f);
        a00 = fma2(pp0, vA.x, a00);
        a01 = fma2(pp0, vA.y, a01);
        a02 = fma2(pp0, vB.x, a02);
        a03 = fma2(pp0, vB.y, a03);
        a10 = fma2(pp1, vA.x, a10);
        a11 = fma2(pp1, vA.y, a11);
        a12 = fma2(pp1, vB.x, a12);
        a13 = fma2(pp1, vB.y, a13);
    }

    float l0, h0, l1, h1, l2, h2, l3, h3;
    int oi0 = ((split * BB + b) * PPB + p0) * 2;
    upk2(a00, l0, h0); upk2(a01, l1, h1); upk2(a02, l2, h2); upk2(a03, l3, h3);
    g_part4[oi0 + 0] = make_float4(l0, h0, l1, h1);
    g_part4[oi0 + 1] = make_float4(l2, h2, l3, h3);
    int oi1 = oi0 + BLKP * 2;
    upk2(a10, l0, h0); upk2(a11, l1, h1); upk2(a12, l2, h2); upk2(a13, l3, h3);
    g_part4[oi1 + 0] = make_float4(l0, h0, l1, h1);
    g_part4[oi1 + 1] = make_float4(l2, h2, l3, h3);
}

// ---------------------------------------------------------------------------
// k5: reduce partials, threshold, project 8->5, write transposed (b, 5, t, n)
// grid: 40 x 256
// ---------------------------------------------------------------------------
__global__ void k5_final(const float* __restrict__ W_out, const float* __restrict__ b_out,
                         float* __restrict__ out) {
    int p = blockIdx.x * 256 + threadIdx.x;
    if (p >= NPTS) return;
    int b = p / PPB, r = p % PPB, t = r / VV, v = r % VV;

    float o[8] = {0, 0, 0, 0, 0, 0, 0, 0};
#pragma unroll 8
    for (int s = 0; s < NSPLIT; s++) {
        int oi = ((s * BB + b) * PPB + r) * 2;
        float4 a0 = g_part4[oi + 0];   // (o0,o4,o1,o5)
        float4 a1 = g_part4[oi + 1];   // (o2,o6,o3,o7)
        o[0] += a0.x; o[4] += a0.y; o[1] += a0.z; o[5] += a0.w;
        o[2] += a1.x; o[6] += a1.y; o[3] += a1.z; o[7] += a1.w;
    }
#pragma unroll
    for (int d = 0; d < 8; d++) o[d] = (o[d] > 0.5f) ? o[d] : 0.f;
#pragma unroll
    for (int dd = 0; dd < 5; dd++) {
        float y = b_out[dd];
#pragma unroll
        for (int d = 0; d < 8; d++) y = fmaf(W_out[dd * 8 + d], o[d], y);
        out[((b * 5 + dd) * TT + t) * VV + v] = y;
    }
}

// ---------------------------------------------------------------------------
extern "C" void kernel_launch(void* const* d_in, const int* in_sizes, int n_in,
                              void* d_out, int out_size) {
    const float* x      = (const float*)d_in[0];
    const float* ac     = (const float*)d_in[1];
    const float* meta   = (const float*)d_in[2];
    const float* W_ih   = (const float*)d_in[3];
    // d_in[4] = W_hh (unused: h0 = 0)
    const float* b_ih   = (const float*)d_in[5];
    const float* b_hh   = (const float*)d_in[6];
    const float* W_comp = (const float*)d_in[7];
    const float* b_comp = (const float*)d_in[8];
    const float* W_fuse = (const float*)d_in[9];
    const float* b_fuse = (const float*)d_in[10];
    const float* W_fc   = (const float*)d_in[11];
    const float* b_fc   = (const float*)d_in[12];
    const float* W_fc2  = (const float*)d_in[13];
    const float* b_fc2  = (const float*)d_in[14];
    const float* W_fc3  = (const float*)d_in[15];
    const float* b_fc3  = (const float*)d_in[16];
    const float* W_out  = (const float*)d_in[17];
    const float* b_out  = (const float*)d_in[18];
    float* out = (float*)d_out;

    k1_prep<<<8, 256>>>(W_fuse, W_comp, b_comp);
    k2_comp2<<<dim3(8, 32), 128>>>(meta);
    k3_qkv<<<40, 256>>>(x, ac, W_ih, b_ih, b_hh, W_fuse, b_fuse,
                        W_fc, b_fc, W_fc2, b_fc2, W_fc3, b_fc3);
    k4_attn<<<dim3(PPB / PTILE, NSPLIT, BB), BLKP>>>();
    k5_final<<<40, 256>>>(W_out, b_out, out);
}